// round 2
// baseline (speedup 1.0000x reference)
#include <cuda_runtime.h>
#include <math.h>

#define BATCH   256
#define DIM     768
#define NVOCAB  100000
#define VTOP    80
#define SEC     (BATCH*DIM)   // 196608 floats per output section

// ---------------- device scratch (static globals; no allocation) ----------------
__device__ float g_inv_norm[NVOCAB];
__device__ float g_x[BATCH*3072];
__device__ float g_h1[BATCH*2304];
__device__ float g_h2[BATCH*1700];
__device__ float g_h3[BATCH*1000];
__device__ float g_raw4[BATCH*DIM];
__device__ float g_model[BATCH*DIM];
__device__ float g_sims[BATCH*NVOCAB];          // ~102 MB
__device__ int   g_topk[BATCH*VTOP];
__device__ float g_word[BATCH*VTOP*DIM];        // ~63 MB
__device__ float g_board[BATCH*26*DIM];         // ~20 MB

__device__ __forceinline__ float warp_sum(float v) {
#pragma unroll
    for (int o = 16; o; o >>= 1) v += __shfl_xor_sync(0xffffffffu, v, o);
    return v;
}

// ---------------- vocab inverse norms ----------------
__global__ __launch_bounds__(256) void vocab_norms(const float* __restrict__ vocab, int NV) {
    int row = blockIdx.x * 8 + (threadIdx.x >> 5);
    int lane = threadIdx.x & 31;
    if (row >= NV) return;
    const float* src = vocab + (size_t)row * DIM;
    float s = 0.f;
#pragma unroll 4
    for (int d = lane; d < DIM; d += 32) { float v = src[d]; s += v * v; }
    s = warp_sum(s);
    if (lane == 0) g_inv_norm[row] = 1.0f / fmaxf(sqrtf(s), 1e-12f);
}

// ---------------- board prep: normalized words + pooled MLP input ----------------
__global__ __launch_bounds__(256) void board_prep(
    const float* __restrict__ pos, const float* __restrict__ neg,
    const float* __restrict__ neut, const float* __restrict__ assas)
{
    int b = blockIdx.x;
    int t = threadIdx.x;
    int warp = t >> 5, lane = t & 31;

    // --- per-word L2-normalized embeddings into g_board, order: pos(0-8) neg(9-17) neut(18-24) assas(25)
    for (int w = warp; w < 26; w += 8) {
        const float* src;
        if (w < 9)       src = pos  + ((size_t)b * 9 + w) * DIM;
        else if (w < 18) src = neg  + ((size_t)b * 9 + (w - 9)) * DIM;
        else if (w < 25) src = neut + ((size_t)b * 7 + (w - 18)) * DIM;
        else             src = assas + (size_t)b * DIM;
        float s = 0.f;
        for (int d = lane; d < DIM; d += 32) { float v = src[d]; s += v * v; }
        s = warp_sum(s);
        float inv = 1.0f / fmaxf(sqrtf(s), 1e-8f);
        float* dst = g_board + ((size_t)b * 26 + w) * DIM;
        for (int d = lane; d < DIM; d += 32) dst[d] = src[d] * inv;
    }

    // --- pooled groups -> g_x[b, 3072]: [neg_pool | assassin_raw | neut_pool | pos_pool]
    __shared__ float red[256];
    float* xb = g_x + (size_t)b * 3072;

    // assassin raw copy
#pragma unroll
    for (int r = 0; r < 3; r++) {
        int d = t + 256 * r;
        xb[768 + d] = assas[(size_t)b * DIM + d];
    }

    const float* srcs[3] = { neg, neut, pos };
    const int nw[3] = { 9, 7, 9 };
    const int xoff[3] = { 0, 1536, 2304 };
    for (int g = 0; g < 3; g++) {
        float m[3];
#pragma unroll
        for (int r = 0; r < 3; r++) {
            int d = t + 256 * r;
            float s = 0.f;
            for (int w = 0; w < nw[g]; w++)
                s += srcs[g][((size_t)b * nw[g] + w) * DIM + d];
            m[r] = s / (float)nw[g];
        }
        red[t] = m[0]*m[0] + m[1]*m[1] + m[2]*m[2];
        __syncthreads();
        for (int s = 128; s > 0; s >>= 1) { if (t < s) red[t] += red[t + s]; __syncthreads(); }
        float inv = 1.0f / fmaxf(sqrtf(red[0]), 1e-12f);
        __syncthreads();
#pragma unroll
        for (int r = 0; r < 3; r++) xb[xoff[g] + t + 256 * r] = m[r] * inv;
    }
}

// ---------------- generic 128x128x8 SGEMM ----------------
// BT=false: C[M,N] = A[M,K] @ B[K,N]   (B row-major [K,N])
// BT=true:  C[M,N] = A[M,K] @ B^T      (B row-major [N,K])
// mode 0: +bias(aux[n]); mode 1: +bias, relu; mode 2: *aux[n] (scale)
template<bool BT>
__global__ __launch_bounds__(256) void sgemm128(
    const float* __restrict__ A, const float* __restrict__ B,
    const float* __restrict__ aux, float* __restrict__ C,
    int M, int N, int K, int mode)
{
    __shared__ float As[8][128];
    __shared__ float Bs[8][128];
    int tid = threadIdx.x;
    int m0 = blockIdx.y * 128, n0 = blockIdx.x * 128;
    int tx = tid & 15, ty = tid >> 4;

    float acc[8][8];
#pragma unroll
    for (int i = 0; i < 8; i++)
#pragma unroll
        for (int j = 0; j < 8; j++) acc[i][j] = 0.f;

    int lr = tid >> 1;            // 0..127
    int lc = (tid & 1) * 4;       // 0 or 4
    int bnr = tid >> 5;           // 0..7 (k row) for NN B
    int bnc = (tid & 31) * 4;     // n offset for NN B

    for (int k0 = 0; k0 < K; k0 += 8) {
        float4 av = make_float4(0.f, 0.f, 0.f, 0.f);
        {
            int gm = m0 + lr, gk = k0 + lc;
            if (gm < M && gk < K) av = *(const float4*)(A + (size_t)gm * K + gk);
        }
        As[lc + 0][lr] = av.x; As[lc + 1][lr] = av.y;
        As[lc + 2][lr] = av.z; As[lc + 3][lr] = av.w;

        if (BT) {
            float4 bv = make_float4(0.f, 0.f, 0.f, 0.f);
            int gn = n0 + lr, gk = k0 + lc;
            if (gn < N && gk < K) bv = *(const float4*)(B + (size_t)gn * K + gk);
            Bs[lc + 0][lr] = bv.x; Bs[lc + 1][lr] = bv.y;
            Bs[lc + 2][lr] = bv.z; Bs[lc + 3][lr] = bv.w;
        } else {
            float4 bv = make_float4(0.f, 0.f, 0.f, 0.f);
            int gk = k0 + bnr, gn = n0 + bnc;
            if (gk < K && gn < N) bv = *(const float4*)(B + (size_t)gk * N + gn);
            *(float4*)&Bs[bnr][bnc] = bv;
        }
        __syncthreads();

#pragma unroll
        for (int kk = 0; kk < 8; kk++) {
            float4 a0 = *(const float4*)&As[kk][ty * 8];
            float4 a1 = *(const float4*)&As[kk][ty * 8 + 4];
            float4 b0 = *(const float4*)&Bs[kk][tx * 8];
            float4 b1 = *(const float4*)&Bs[kk][tx * 8 + 4];
            float ar[8] = { a0.x, a0.y, a0.z, a0.w, a1.x, a1.y, a1.z, a1.w };
            float br[8] = { b0.x, b0.y, b0.z, b0.w, b1.x, b1.y, b1.z, b1.w };
#pragma unroll
            for (int i = 0; i < 8; i++)
#pragma unroll
                for (int j = 0; j < 8; j++)
                    acc[i][j] += ar[i] * br[j];
        }
        __syncthreads();
    }

#pragma unroll
    for (int i = 0; i < 8; i++) {
        int gm = m0 + ty * 8 + i;
        if (gm >= M) continue;
#pragma unroll
        for (int j = 0; j < 8; j++) {
            int gn = n0 + tx * 8 + j;
            if (gn >= N) continue;
            float v = acc[i][j];
            if (mode == 2) v *= aux[gn];
            else { v += aux[gn]; if (mode == 1) v = fmaxf(v, 0.f); }
            C[(size_t)gm * N + gn] = v;
        }
    }
}

// ---------------- row L2 normalize of raw layer-4 output -> g_model and out[sec0] ----------------
__global__ __launch_bounds__(256) void norm_rows(float* __restrict__ out) {
    int b = blockIdx.x, t = threadIdx.x;
    __shared__ float red[256];
    const float* in = g_raw4 + (size_t)b * DIM;
    float v0 = in[t], v1 = in[t + 256], v2 = in[t + 512];
    red[t] = v0 * v0 + v1 * v1 + v2 * v2;
    __syncthreads();
    for (int s = 128; s > 0; s >>= 1) { if (t < s) red[t] += red[t + s]; __syncthreads(); }
    float inv = 1.0f / fmaxf(sqrtf(red[0]), 1e-12f);
    float* gm = g_model + (size_t)b * DIM;
    float* om = out + (size_t)b * DIM;
    gm[t] = v0 * inv;        om[t] = v0 * inv;
    gm[t + 256] = v1 * inv;  om[t + 256] = v1 * inv;
    gm[t + 512] = v2 * inv;  om[t + 512] = v2 * inv;
}

// ---------------- top-80 per row: histogram threshold + exact rank select ----------------
__global__ __launch_bounds__(256) void topk_kernel(int NV) {
    __shared__ unsigned int hist[2048];
    __shared__ float cval[2048];
    __shared__ int   cidx[2048];
    __shared__ int s_cnt, s_thr;
    int b = blockIdx.x, t = threadIdx.x;
    for (int i = t; i < 2048; i += 256) hist[i] = 0;
    if (t == 0) s_cnt = 0;
    __syncthreads();

    const float* row = g_sims + (size_t)b * NV;
    for (int n = t; n < NV; n += 256) {
        float v = row[n];
        int bin = (int)((v + 1.0f) * 1024.0f);
        bin = min(max(bin, 0), 2047);
        atomicAdd(&hist[bin], 1u);
    }
    __syncthreads();
    if (t == 0) {
        unsigned int c = 0; int bin = 2047;
        for (; bin >= 0; bin--) { c += hist[bin]; if (c >= VTOP) break; }
        s_thr = bin;
    }
    __syncthreads();
    int thr = s_thr;
    for (int n = t; n < NV; n += 256) {
        float v = row[n];
        int bin = (int)((v + 1.0f) * 1024.0f);
        bin = min(max(bin, 0), 2047);
        if (bin >= thr) {
            int p = atomicAdd(&s_cnt, 1);
            if (p < 2048) { cval[p] = v; cidx[p] = n; }
        }
    }
    __syncthreads();
    int C = min(s_cnt, 2048);
    // exact rank with lax.top_k tie-break: value desc, index asc
    for (int i = t; i < C; i += 256) {
        float vi = cval[i]; int ii = cidx[i];
        int r = 0;
        for (int j = 0; j < C; j++) {
            float vj = cval[j];
            r += (vj > vi) || (vj == vi && cidx[j] < ii);
        }
        if (r < VTOP) g_topk[b * VTOP + r] = ii;
    }
}

// ---------------- gather normalized word embeddings; write out[sec1] for v==0 ----------------
__global__ __launch_bounds__(256) void gather_kernel(const float* __restrict__ vocab, float* __restrict__ out) {
    int v = blockIdx.x, b = blockIdx.y, t = threadIdx.x;
    int idx = g_topk[b * VTOP + v];
    float inv = g_inv_norm[idx];
    const float* src = vocab + (size_t)idx * DIM;
    float* dst = g_word + ((size_t)b * VTOP + v) * DIM;
    for (int d = t; d < DIM; d += 256) {
        float val = src[d] * inv;
        dst[d] = val;
        if (v == 0) out[SEC + (size_t)b * DIM + d] = val;
    }
}

// ---------------- scoring + reward + selection + pooling ----------------
__global__ __launch_bounds__(256) void score_kernel(float* __restrict__ out) {
    int b = blockIdx.x, t = threadIdx.x;
    int warp = t >> 5, lane = t & 31;
    __shared__ float S[VTOP][26];
    __shared__ float tot[VTOP];
    __shared__ unsigned char inmax[VTOP], inmin[VTOP];
    __shared__ float red[256];

    // Phase A: cosine scores S[v][j] = word_v . board_j (both unit vectors)
    for (int v = warp; v < VTOP; v += 8) {
        if (lane < 26) {
            const float4* w = (const float4*)(g_word + ((size_t)b * VTOP + v) * DIM);
            const float4* brd = (const float4*)(g_board + ((size_t)b * 26 + lane) * DIM);
            float acc = 0.f;
#pragma unroll 8
            for (int d = 0; d < DIM / 4; d++) {
                float4 a = w[d], c = brd[d];
                acc += a.x * c.x + a.y * c.y + a.z * c.z + a.w * c.w;
            }
            S[v][lane] = acc;
        }
    }
    __syncthreads();

    // Phase B: num_correct, secondary reward, tot (exact small floats)
    if (t < VTOP) {
        float maxbad = -1e30f;
#pragma unroll
        for (int j = 9; j < 26; j++) maxbad = fmaxf(maxbad, S[t][j]);
        int nc = 0;
#pragma unroll
        for (int j = 0; j < 9; j++) nc += (S[t][j] >= maxbad) ? 1 : 0;
        int jm = 25;
        for (int j = 9; j < 26; j++) { if (S[t][j] == maxbad) { jm = j; break; } }
        float sec = (jm <= 17) ? 0.0f : ((jm <= 24) ? 1.0f : -10.0f);
        tot[t] = (float)nc + sec;
    }
    __syncthreads();

    // Phase C: top-40 / bottom-40 selection with stable tie-break (lower index first)
    if (t < VTOP) {
        float tv = tot[t];
        int rmax = 0, rmin = 0;
        for (int u = 0; u < VTOP; u++) {
            float tu = tot[u];
            rmax += (tu > tv) || (tu == tv && u < t);
            rmin += (tu < tv) || (tu == tv && u < t);
        }
        inmax[t] = (rmax < VTOP / 2);
        inmin[t] = (rmin < VTOP / 2);
    }
    __syncthreads();

    // Phase D: pool selected embeddings -> mean -> normalize -> out[sec2], out[sec3]
    float smax[3] = {0.f, 0.f, 0.f}, smin[3] = {0.f, 0.f, 0.f};
    for (int v = 0; v < VTOP; v++) {
        const float* w = g_word + ((size_t)b * VTOP + v) * DIM;
        bool fx = inmax[v], fn = inmin[v];
#pragma unroll
        for (int r = 0; r < 3; r++) {
            float val = w[t + 256 * r];
            if (fx) smax[r] += val;
            if (fn) smin[r] += val;
        }
    }
#pragma unroll
    for (int r = 0; r < 3; r++) { smax[r] *= (1.0f / 40.0f); smin[r] *= (1.0f / 40.0f); }

    red[t] = smax[0]*smax[0] + smax[1]*smax[1] + smax[2]*smax[2];
    __syncthreads();
    for (int s = 128; s > 0; s >>= 1) { if (t < s) red[t] += red[t + s]; __syncthreads(); }
    float invx = 1.0f / fmaxf(sqrtf(red[0]), 1e-12f);
    __syncthreads();
#pragma unroll
    for (int r = 0; r < 3; r++) out[2 * SEC + (size_t)b * DIM + t + 256 * r] = smax[r] * invx;

    red[t] = smin[0]*smin[0] + smin[1]*smin[1] + smin[2]*smin[2];
    __syncthreads();
    for (int s = 128; s > 0; s >>= 1) { if (t < s) red[t] += red[t + s]; __syncthreads(); }
    float invn = 1.0f / fmaxf(sqrtf(red[0]), 1e-12f);
    __syncthreads();
#pragma unroll
    for (int r = 0; r < 3; r++) out[3 * SEC + (size_t)b * DIM + t + 256 * r] = smin[r] * invn;
}

// ---------------- launch ----------------
extern "C" void kernel_launch(void* const* d_in, const int* in_sizes, int n_in,
                              void* d_out, int out_size)
{
    const float* pos   = (const float*)d_in[0];
    const float* neg   = (const float*)d_in[1];
    const float* neut  = (const float*)d_in[2];
    const float* assas = (const float*)d_in[3];
    const float* vocab = (const float*)d_in[4];
    const float* W1 = (const float*)d_in[5];  const float* b1 = (const float*)d_in[6];
    const float* W2 = (const float*)d_in[7];  const float* b2 = (const float*)d_in[8];
    const float* W3 = (const float*)d_in[9];  const float* b3 = (const float*)d_in[10];
    const float* W4 = (const float*)d_in[11]; const float* b4 = (const float*)d_in[12];
    float* out = (float*)d_out;
    int NV = in_sizes[4] / DIM;

    float *p_x, *p_h1, *p_h2, *p_h3, *p_raw4, *p_model, *p_sims, *p_inv;
    cudaGetSymbolAddress((void**)&p_x,     g_x);
    cudaGetSymbolAddress((void**)&p_h1,    g_h1);
    cudaGetSymbolAddress((void**)&p_h2,    g_h2);
    cudaGetSymbolAddress((void**)&p_h3,    g_h3);
    cudaGetSymbolAddress((void**)&p_raw4,  g_raw4);
    cudaGetSymbolAddress((void**)&p_model, g_model);
    cudaGetSymbolAddress((void**)&p_sims,  g_sims);
    cudaGetSymbolAddress((void**)&p_inv,   g_inv_norm);

    vocab_norms<<<(NV + 7) / 8, 256>>>(vocab, NV);
    board_prep<<<BATCH, 256>>>(pos, neg, neut, assas);

    dim3 g1((2304 + 127) / 128, 2);
    sgemm128<false><<<g1, 256>>>(p_x,  W1, b1, p_h1,   BATCH, 2304, 3072, 1);
    dim3 g2((1700 + 127) / 128, 2);
    sgemm128<false><<<g2, 256>>>(p_h1, W2, b2, p_h2,   BATCH, 1700, 2304, 1);
    dim3 g3((1000 + 127) / 128, 2);
    sgemm128<false><<<g3, 256>>>(p_h2, W3, b3, p_h3,   BATCH, 1000, 1700, 1);
    dim3 g4((768 + 127) / 128, 2);
    sgemm128<false><<<g4, 256>>>(p_h3, W4, b4, p_raw4, BATCH, 768, 1000, 0);

    norm_rows<<<BATCH, 256>>>(out);

    dim3 gs((NV + 127) / 128, 2);
    sgemm128<true><<<gs, 256>>>(p_model, vocab, p_inv, p_sims, BATCH, NV, DIM, 2);

    topk_kernel<<<BATCH, 256>>>(NV);
    gather_kernel<<<dim3(VTOP, BATCH), 256>>>(vocab, out);
    score_kernel<<<BATCH, 256>>>(out);
}